// round 2
// baseline (speedup 1.0000x reference)
#include <cuda_runtime.h>
#include <cstdint>

#define N_NODES 100000
#define N_EDGES 1250000
#define D 64

// Scratch: aggregation buffer (reused for both layers). 25.6 MB.
__device__ float g_agg[(size_t)N_NODES * D];
__device__ int g_is64;

// ---------------------------------------------------------------------------
// Detect whether edge_index is int64 or int32 on device.
// If int64 (little-endian, values < 2^31), every odd 32-bit word is 0.
// If int32, odd words are random indices (all-zero prob ~1e-320).
// ---------------------------------------------------------------------------
__global__ void detect_kernel(const unsigned* __restrict__ ei) {
    if (threadIdx.x == 0 && blockIdx.x == 0) {
        int all0 = 1;
        #pragma unroll 1
        for (int i = 0; i < 64; i++) {
            if (ei[2 * i + 1] != 0u) { all0 = 0; break; }
        }
        g_is64 = all0;
    }
}

// ---------------------------------------------------------------------------
// Zero the aggregation buffer (float4 stores).
// ---------------------------------------------------------------------------
__global__ void zero_kernel() {
    int i = blockIdx.x * blockDim.x + threadIdx.x;
    const int n = N_NODES * D / 4;
    if (i < n) {
        reinterpret_cast<float4*>(g_agg)[i] = make_float4(0.f, 0.f, 0.f, 0.f);
    }
}

// ---------------------------------------------------------------------------
// Scatter-add: g_agg[dst] += h[src] for each edge.
// 16 threads per edge, each handles one float4 chunk of the 64-wide row.
// Uses red.global.add.v4.f32 (no return value, 4x fewer L2 atomic ops).
// ---------------------------------------------------------------------------
__global__ void scatter_kernel(const float* __restrict__ h,
                               const void* __restrict__ ei) {
    int tid = blockIdx.x * blockDim.x + threadIdx.x;
    int e = tid >> 4;
    int c = tid & 15;
    if (e >= N_EDGES) return;

    long long s, d;
    if (g_is64) {
        const long long* p = (const long long*)ei;
        s = p[e];
        d = p[e + N_EDGES];
    } else {
        const int* p = (const int*)ei;
        s = p[e];
        d = p[e + N_EDGES];
    }

    float4 v = *reinterpret_cast<const float4*>(h + s * D + c * 4);
    float* dstp = g_agg + d * D + c * 4;
    unsigned long long ga = (unsigned long long)__cvta_generic_to_global(dstp);
    asm volatile("red.global.add.v4.f32 [%0], {%1,%2,%3,%4};"
                 :: "l"(ga), "f"(v.x), "f"(v.y), "f"(v.z), "f"(v.w)
                 : "memory");
}

// ---------------------------------------------------------------------------
// Linear: out[i][j] = sum_k g_agg[i][k] * W[j][k] + b[j]
// One block handles 32 rows. W cached in smem with pad-68 rows so float4
// loads are bank-conflict-free. As reads are warp-uniform (broadcast).
// ---------------------------------------------------------------------------
__global__ void linear_kernel(float* __restrict__ out,
                              const float* __restrict__ W,
                              const float* __restrict__ b) {
    __shared__ float Ws[D * 68];       // row j at Ws + j*68 (272B, 16B-aligned)
    __shared__ float As[32 * D];       // 32 input rows

    const int t = threadIdx.x;         // 256 threads
    const int row0 = blockIdx.x * 32;

    // Load W [64x64] into padded smem
    #pragma unroll 4
    for (int i = t; i < D * D; i += 256) {
        int j = i >> 6, k = i & 63;
        Ws[j * 68 + k] = W[i];
    }
    // Load 32 rows of g_agg (512 float4s)
    const float4* src4 = reinterpret_cast<const float4*>(g_agg + (size_t)row0 * D);
    float4* As4 = reinterpret_cast<float4*>(As);
    #pragma unroll 2
    for (int i = t; i < 32 * D / 4; i += 256) {
        As4[i] = src4[i];
    }
    __syncthreads();

    const int j  = t & 63;             // output column (warp-contiguous)
    const int rq = t >> 6;             // row phase 0..3
    const float bj = __ldg(b + j);
    const float4* Wj = reinterpret_cast<const float4*>(Ws + j * 68);

    #pragma unroll
    for (int r = rq; r < 32; r += 4) {
        const float4* Ar = reinterpret_cast<const float4*>(As + r * D);
        float acc = 0.f;
        #pragma unroll
        for (int k4 = 0; k4 < D / 4; k4++) {
            float4 w = Wj[k4];
            float4 a = Ar[k4];         // warp-uniform -> smem broadcast
            acc += w.x * a.x + w.y * a.y + w.z * a.z + w.w * a.w;
        }
        out[(size_t)(row0 + r) * D + j] = acc + bj;
    }
}

// ---------------------------------------------------------------------------
extern "C" void kernel_launch(void* const* d_in, const int* in_sizes, int n_in,
                              void* d_out, int out_size) {
    const float* x  = (const float*)d_in[0];
    const void*  ei = d_in[1];
    const float* W1 = (const float*)d_in[2];
    const float* b1 = (const float*)d_in[3];

    float* out = (float*)d_out;                      // first N*D elements
    float* hid = out + (size_t)N_NODES * D;          // second N*D elements

    const int ZBLK = (N_NODES * D / 4 + 255) / 256;
    const int SBLK = (N_EDGES * 16 + 255) / 256;
    const int LBLK = N_NODES / 32;                   // 3125

    detect_kernel<<<1, 1>>>((const unsigned*)ei);

    // Layer 1: hid = scatter_add(x) @ W1^T + b1
    zero_kernel<<<ZBLK, 256>>>();
    scatter_kernel<<<SBLK, 256>>>(x, ei);
    linear_kernel<<<LBLK, 256>>>(hid, W1, b1);

    // Layer 2: out = scatter_add(hid) @ W1^T + b1
    zero_kernel<<<ZBLK, 256>>>();
    scatter_kernel<<<SBLK, 256>>>(hid, ei);
    linear_kernel<<<LBLK, 256>>>(out, W1, b1);
}